// round 1
// baseline (speedup 1.0000x reference)
#include <cuda_runtime.h>

// Problem constants
#define BB 2
#define SS 2048
#define DD 1024
#define HH 16
#define KH 64            // d_head
#define NBH (BB*HH)      // 32
#define PAD 68           // padded row stride (floats) for transposed smem tiles

// Scratch (device globals — allocation-free rule)
__device__ float g_Q  [(size_t)NBH * SS * KH];
__device__ float g_Kp [(size_t)NBH * SS * KH];
__device__ float g_V  [(size_t)NBH * SS * KH];
__device__ float g_ctx[(size_t)NBH * SS * KH];

__device__ __forceinline__ void fma44(float acc[4][4], float4 a, float4 b) {
    float av[4] = {a.x, a.y, a.z, a.w};
    float bv[4] = {b.x, b.y, b.z, b.w};
#pragma unroll
    for (int i = 0; i < 4; i++)
#pragma unroll
        for (int j = 0; j < 4; j++)
            acc[i][j] = fmaf(av[i], bv[j], acc[i][j]);
}

// ---------------------------------------------------------------------------
// Kernel 1: QKV projection.  For each (b, h, {q,k,v}): [2048,1024]@[1024,64].
// Block: 64 rows of S x full 64 cols.  256 threads, 4x4 microtile each.
// ---------------------------------------------------------------------------
__global__ __launch_bounds__(256) void qkv_gemm(const float* __restrict__ x,
                                                const float* __restrict__ Wq,
                                                const float* __restrict__ Wk,
                                                const float* __restrict__ Wv) {
    __shared__ float As[16][PAD];  // transposed A tile: As[k][row]
    __shared__ float Bs[16][64];   // B tile: Bs[k][col]

    const int t  = threadIdx.x;
    const int tx = t & 15, ty = t >> 4;
    const int s0 = blockIdx.x * 64;
    const int bh = blockIdx.y;
    const int b  = bh >> 4;        // H == 16
    const int h  = bh & 15;

    const float* W = (blockIdx.z == 0) ? Wq : (blockIdx.z == 1) ? Wk : Wv;
    float*       O = (blockIdx.z == 0) ? g_Q : (blockIdx.z == 1) ? g_Kp : g_V;
    const float* Wh = W + (size_t)h * DD * KH;
    const float* A  = x + ((size_t)b * SS + s0) * DD;

    float acc[4][4] = {};

    const int lc  = t & 15, lr0 = t >> 4;  // A loader: col in chunk, base row
    const int bc  = t & 63, br  = t >> 6;  // B loader

    for (int k0 = 0; k0 < DD; k0 += 16) {
#pragma unroll
        for (int i = 0; i < 4; i++) {
            int r = lr0 + i * 16;
            As[lc][r] = A[(size_t)r * DD + k0 + lc];
        }
#pragma unroll
        for (int i = 0; i < 4; i++) {
            int rr = br + i * 4;
            Bs[rr][bc] = Wh[(size_t)(k0 + rr) * KH + bc];
        }
        __syncthreads();
#pragma unroll
        for (int kk = 0; kk < 16; kk++) {
            float4 a  = *(const float4*)&As[kk][ty * 4];
            float4 b4 = *(const float4*)&Bs[kk][tx * 4];
            fma44(acc, a, b4);
        }
        __syncthreads();
    }

    float* Orow = O + ((size_t)bh * SS + s0) * KH;
#pragma unroll
    for (int i = 0; i < 4; i++) {
        float4 v = make_float4(acc[i][0], acc[i][1], acc[i][2], acc[i][3]);
        *(float4*)&Orow[(size_t)(ty * 4 + i) * KH + tx * 4] = v;
    }
}

// ---------------------------------------------------------------------------
// Kernel 2: flash attention, one (b,h) x 64-query-row tile per block.
// Online softmax; P tile reuses the K smem buffer.  256 threads, 4x4/thread.
// ---------------------------------------------------------------------------
#define SMEM_ATTN_FLOATS (64*PAD /*Qts*/ + 64*PAD /*K/P*/ + 64*64 /*V*/ + 64*16 /*redM*/ + 64*16 /*redS*/)
#define SMEM_ATTN_BYTES  (SMEM_ATTN_FLOATS * 4)

__global__ __launch_bounds__(256) void attn_kernel() {
    extern __shared__ float sm[];
    float* Qts  = sm;                 // [64][PAD]  Qts[k][row] (pre-scaled)
    float* KPs  = Qts + 64 * PAD;     // [64][PAD]  K: KPs[k][col]; later P: KPs[key][row]
    float* Vs   = KPs + 64 * PAD;     // [64][64]   Vs[key][col]
    float* redM = Vs + 64 * 64;       // [64][16]
    float* redS = redM + 64 * 16;     // [64][16]

    const int t  = threadIdx.x;
    const int tx = t & 15, ty = t >> 4;
    const int bh = blockIdx.y;
    const int q0 = blockIdx.x * 64;

    const float* Qg = g_Q  + ((size_t)bh * SS + q0) * KH;
    const float* Kg = g_Kp + (size_t)bh * SS * KH;
    const float* Vg = g_V  + (size_t)bh * SS * KH;

    // Load Q transposed, pre-scaled by 1/sqrt(64)
    {
        const int c = t & 63, r0 = t >> 6;
#pragma unroll
        for (int i = 0; i < 16; i++) {
            int r = r0 + i * 4;
            Qts[c * PAD + r] = Qg[(size_t)r * KH + c] * 0.125f;
        }
    }

    float m[4], l[4], o[4][4];
#pragma unroll
    for (int i = 0; i < 4; i++) {
        m[i] = -1e30f; l[i] = 0.f;
#pragma unroll
        for (int j = 0; j < 4; j++) o[i][j] = 0.f;
    }

    for (int j0 = 0; j0 < SS; j0 += 64) {
        __syncthreads();  // prior iter done with KPs/Vs/redM/redS
        {
            const int c = t & 63, r0 = t >> 6;
#pragma unroll
            for (int i = 0; i < 16; i++) {
                int r = r0 + i * 4;
                KPs[c * PAD + r] = Kg[(size_t)(j0 + r) * KH + c];   // transposed
                Vs[r * 64 + c]   = Vg[(size_t)(j0 + r) * KH + c];   // row-major
            }
        }
        __syncthreads();

        // S = (Q * scale) @ K^T for this 64x64 tile
        float s[4][4] = {};
#pragma unroll
        for (int kk = 0; kk < 64; kk++) {
            float4 a = *(const float4*)&Qts[kk * PAD + ty * 4];
            float4 b = *(const float4*)&KPs[kk * PAD + tx * 4];
            fma44(s, a, b);
        }

        // row-max reduction (partial -> smem -> full)
#pragma unroll
        for (int i = 0; i < 4; i++) {
            float pm = fmaxf(fmaxf(s[i][0], s[i][1]), fmaxf(s[i][2], s[i][3]));
            redM[(ty * 4 + i) * 16 + tx] = pm;
        }
        __syncthreads();  // score reads of KPs also complete here

        float mn[4];
#pragma unroll
        for (int i = 0; i < 4; i++) {
            int row = ty * 4 + i;
            float v = redM[row * 16];
#pragma unroll
            for (int u = 1; u < 16; u++) v = fmaxf(v, redM[row * 16 + u]);
            mn[i] = fmaxf(m[i], v);
        }

        // P = exp(S - m_new); store transposed into KPs (safe: K reads done)
#pragma unroll
        for (int i = 0; i < 4; i++) {
            float ps = 0.f;
#pragma unroll
            for (int j = 0; j < 4; j++) {
                float p = __expf(s[i][j] - mn[i]);
                KPs[(tx * 4 + j) * PAD + ty * 4 + i] = p;  // KPs[key][row]
                ps += p;
            }
            redS[(ty * 4 + i) * 16 + tx] = ps;
        }
        __syncthreads();

        // update running stats, rescale O
#pragma unroll
        for (int i = 0; i < 4; i++) {
            int row = ty * 4 + i;
            float rs = 0.f;
#pragma unroll
            for (int u = 0; u < 16; u++) rs += redS[row * 16 + u];
            float f = __expf(m[i] - mn[i]);
            l[i] = l[i] * f + rs;
            m[i] = mn[i];
#pragma unroll
            for (int j = 0; j < 4; j++) o[i][j] *= f;
        }

        // O += P @ V
#pragma unroll
        for (int tt = 0; tt < 64; tt++) {
            float4 a = *(const float4*)&KPs[tt * PAD + ty * 4];  // P[row][tt]
            float4 b = *(const float4*)&Vs[tt * 64 + tx * 4];
            fma44(o, a, b);
        }
    }

    float* C = g_ctx + ((size_t)bh * SS + q0) * KH;
#pragma unroll
    for (int i = 0; i < 4; i++) {
        float inv = 1.f / l[i];
        float4 v = make_float4(o[i][0] * inv, o[i][1] * inv, o[i][2] * inv, o[i][3] * inv);
        *(float4*)&C[(size_t)(ty * 4 + i) * KH + tx * 4] = v;
    }
}

// ---------------------------------------------------------------------------
// Kernel 3: output projection + head sum.
// out[B*S, D] = ctx_view[B*S, H*K] @ Wo_view[H*K, D]
// ---------------------------------------------------------------------------
__global__ __launch_bounds__(256) void out_gemm(const float* __restrict__ Wo,
                                                float* __restrict__ out) {
    __shared__ float As[16][PAD];
    __shared__ float Bs[16][64];

    const int t  = threadIdx.x;
    const int tx = t & 15, ty = t >> 4;
    const int m0 = blockIdx.x * 64;
    const int n0 = blockIdx.y * 64;

    float acc[4][4] = {};

    const int lc = t & 15, lr0 = t >> 4;
    const int bc = t & 63, br  = t >> 6;

    for (int k0 = 0; k0 < DD; k0 += 16) {
        const int h   = k0 >> 6;   // 16-chunk stays within one head
        const int kk0 = k0 & 63;
#pragma unroll
        for (int i = 0; i < 4; i++) {
            int r = lr0 + i * 16;
            int mrow = m0 + r;
            int b = mrow >> 11;          // S == 2048
            int s = mrow & 2047;
            As[lc][r] = g_ctx[(((size_t)(b * HH + h)) * SS + s) * KH + kk0 + lc];
        }
#pragma unroll
        for (int i = 0; i < 4; i++) {
            int rr = br + i * 4;
            Bs[rr][bc] = Wo[(size_t)(k0 + rr) * DD + n0 + bc];
        }
        __syncthreads();
#pragma unroll
        for (int kk = 0; kk < 16; kk++) {
            float4 a  = *(const float4*)&As[kk][ty * 4];
            float4 b4 = *(const float4*)&Bs[kk][tx * 4];
            fma44(acc, a, b4);
        }
        __syncthreads();
    }

#pragma unroll
    for (int i = 0; i < 4; i++) {
        float4 v = make_float4(acc[i][0], acc[i][1], acc[i][2], acc[i][3]);
        *(float4*)&out[(size_t)(m0 + ty * 4 + i) * DD + n0 + tx * 4] = v;
    }
}

// ---------------------------------------------------------------------------
extern "C" void kernel_launch(void* const* d_in, const int* in_sizes, int n_in,
                              void* d_out, int out_size) {
    const float* x  = (const float*)d_in[0];
    const float* Wq = (const float*)d_in[1];
    const float* Wk = (const float*)d_in[2];
    const float* Wv = (const float*)d_in[3];
    const float* Wo = (const float*)d_in[4];
    float* out = (float*)d_out;

    cudaFuncSetAttribute(attn_kernel, cudaFuncAttributeMaxDynamicSharedMemorySize,
                         SMEM_ATTN_BYTES);

    qkv_gemm<<<dim3(SS / 64, NBH, 3), 256>>>(x, Wq, Wk, Wv);
    attn_kernel<<<dim3(SS / 64, NBH), 256, SMEM_ATTN_BYTES>>>();
    out_gemm<<<dim3((BB * SS) / 64, DD / 64), 256>>>(Wo, out);
}

// round 2
// speedup vs baseline: 1.0559x; 1.0559x over previous
#include <cuda_runtime.h>

// Problem constants
#define BB 2
#define SS 2048
#define DD 1024
#define HH 16
#define KH 64            // d_head
#define NBH (BB*HH)      // 32
#define PAD 68           // padded row stride (floats) for transposed smem tiles

// Scratch (device globals — allocation-free rule)
__device__ float g_Q  [(size_t)NBH * SS * KH];
__device__ float g_Kp [(size_t)NBH * SS * KH];
__device__ float g_V  [(size_t)NBH * SS * KH];
__device__ float g_ctx[(size_t)NBH * SS * KH];

__device__ __forceinline__ void fma44(float acc[4][4], float4 a, float4 b) {
    float av[4] = {a.x, a.y, a.z, a.w};
    float bv[4] = {b.x, b.y, b.z, b.w};
#pragma unroll
    for (int i = 0; i < 4; i++)
#pragma unroll
        for (int j = 0; j < 4; j++)
            acc[i][j] = fmaf(av[i], bv[j], acc[i][j]);
}

// ---------------------------------------------------------------------------
// Kernel 1: QKV projection.  For each (b, h, {q,k,v}): [2048,1024]@[1024,64].
// Block: 64 rows of S x full 64 cols.  256 threads, 4x4 microtile each.
// ---------------------------------------------------------------------------
__global__ __launch_bounds__(256) void qkv_gemm(const float* __restrict__ x,
                                                const float* __restrict__ Wq,
                                                const float* __restrict__ Wk,
                                                const float* __restrict__ Wv) {
    __shared__ float As[16][PAD];  // transposed A tile: As[k][row]
    __shared__ float Bs[16][64];   // B tile: Bs[k][col]

    const int t  = threadIdx.x;
    const int tx = t & 15, ty = t >> 4;
    const int s0 = blockIdx.x * 64;
    const int bh = blockIdx.y;
    const int b  = bh >> 4;        // H == 16
    const int h  = bh & 15;

    const float* W = (blockIdx.z == 0) ? Wq : (blockIdx.z == 1) ? Wk : Wv;
    float*       O = (blockIdx.z == 0) ? g_Q : (blockIdx.z == 1) ? g_Kp : g_V;
    const float* Wh = W + (size_t)h * DD * KH;
    const float* A  = x + ((size_t)b * SS + s0) * DD;

    float acc[4][4] = {};

    const int lc  = t & 15, lr0 = t >> 4;  // A loader: col in chunk, base row
    const int bc  = t & 63, br  = t >> 6;  // B loader

    for (int k0 = 0; k0 < DD; k0 += 16) {
#pragma unroll
        for (int i = 0; i < 4; i++) {
            int r = lr0 + i * 16;
            As[lc][r] = A[(size_t)r * DD + k0 + lc];
        }
#pragma unroll
        for (int i = 0; i < 4; i++) {
            int rr = br + i * 4;
            Bs[rr][bc] = Wh[(size_t)(k0 + rr) * KH + bc];
        }
        __syncthreads();
#pragma unroll
        for (int kk = 0; kk < 16; kk++) {
            float4 a  = *(const float4*)&As[kk][ty * 4];
            float4 b4 = *(const float4*)&Bs[kk][tx * 4];
            fma44(acc, a, b4);
        }
        __syncthreads();
    }

    float* Orow = O + ((size_t)bh * SS + s0) * KH;
#pragma unroll
    for (int i = 0; i < 4; i++) {
        float4 v = make_float4(acc[i][0], acc[i][1], acc[i][2], acc[i][3]);
        *(float4*)&Orow[(size_t)(ty * 4 + i) * KH + tx * 4] = v;
    }
}

// ---------------------------------------------------------------------------
// Kernel 2: flash attention, one (b,h) x 64-query-row tile per block.
// Online softmax; P tile reuses the K smem buffer.  256 threads, 4x4/thread.
// ---------------------------------------------------------------------------
#define SMEM_ATTN_FLOATS (64*PAD /*Qts*/ + 64*PAD /*K/P*/ + 64*64 /*V*/ + 64*16 /*redM*/ + 64*16 /*redS*/)
#define SMEM_ATTN_BYTES  (SMEM_ATTN_FLOATS * 4)

__global__ __launch_bounds__(256) void attn_kernel() {
    extern __shared__ float sm[];
    float* Qts  = sm;                 // [64][PAD]  Qts[k][row] (pre-scaled)
    float* KPs  = Qts + 64 * PAD;     // [64][PAD]  K: KPs[k][col]; later P: KPs[key][row]
    float* Vs   = KPs + 64 * PAD;     // [64][64]   Vs[key][col]
    float* redM = Vs + 64 * 64;       // [64][16]
    float* redS = redM + 64 * 16;     // [64][16]

    const int t  = threadIdx.x;
    const int tx = t & 15, ty = t >> 4;
    const int bh = blockIdx.y;
    const int q0 = blockIdx.x * 64;

    const float* Qg = g_Q  + ((size_t)bh * SS + q0) * KH;
    const float* Kg = g_Kp + (size_t)bh * SS * KH;
    const float* Vg = g_V  + (size_t)bh * SS * KH;

    // Load Q transposed, pre-scaled by 1/sqrt(64)
    {
        const int c = t & 63, r0 = t >> 6;
#pragma unroll
        for (int i = 0; i < 16; i++) {
            int r = r0 + i * 4;
            Qts[c * PAD + r] = Qg[(size_t)r * KH + c] * 0.125f;
        }
    }

    float m[4], l[4], o[4][4];
#pragma unroll
    for (int i = 0; i < 4; i++) {
        m[i] = -1e30f; l[i] = 0.f;
#pragma unroll
        for (int j = 0; j < 4; j++) o[i][j] = 0.f;
    }

    for (int j0 = 0; j0 < SS; j0 += 64) {
        __syncthreads();  // prior iter done with KPs/Vs/redM/redS
        {
            const int c = t & 63, r0 = t >> 6;
#pragma unroll
            for (int i = 0; i < 16; i++) {
                int r = r0 + i * 4;
                KPs[c * PAD + r] = Kg[(size_t)(j0 + r) * KH + c];   // transposed
                Vs[r * 64 + c]   = Vg[(size_t)(j0 + r) * KH + c];   // row-major
            }
        }
        __syncthreads();

        // S = (Q * scale) @ K^T for this 64x64 tile
        float s[4][4] = {};
#pragma unroll
        for (int kk = 0; kk < 64; kk++) {
            float4 a = *(const float4*)&Qts[kk * PAD + ty * 4];
            float4 b = *(const float4*)&KPs[kk * PAD + tx * 4];
            fma44(s, a, b);
        }

        // row-max reduction (partial -> smem -> full)
#pragma unroll
        for (int i = 0; i < 4; i++) {
            float pm = fmaxf(fmaxf(s[i][0], s[i][1]), fmaxf(s[i][2], s[i][3]));
            redM[(ty * 4 + i) * 16 + tx] = pm;
        }
        __syncthreads();  // score reads of KPs also complete here

        float mn[4];
#pragma unroll
        for (int i = 0; i < 4; i++) {
            int row = ty * 4 + i;
            float v = redM[row * 16];
#pragma unroll
            for (int u = 1; u < 16; u++) v = fmaxf(v, redM[row * 16 + u]);
            mn[i] = fmaxf(m[i], v);
        }

        // P = exp(S - m_new); store transposed into KPs (safe: K reads done)
#pragma unroll
        for (int i = 0; i < 4; i++) {
            float ps = 0.f;
#pragma unroll
            for (int j = 0; j < 4; j++) {
                float p = __expf(s[i][j] - mn[i]);
                KPs[(tx * 4 + j) * PAD + ty * 4 + i] = p;  // KPs[key][row]
                ps += p;
            }
            redS[(ty * 4 + i) * 16 + tx] = ps;
        }
        __syncthreads();

        // update running stats, rescale O
#pragma unroll
        for (int i = 0; i < 4; i++) {
            int row = ty * 4 + i;
            float rs = 0.f;
#pragma unroll
            for (int u = 0; u < 16; u++) rs += redS[row * 16 + u];
            float f = __expf(m[i] - mn[i]);
            l[i] = l[i] * f + rs;
            m[i] = mn[i];
#pragma unroll
            for (int j = 0; j < 4; j++) o[i][j] *= f;
        }

        // O += P @ V
#pragma unroll
        for (int tt = 0; tt < 64; tt++) {
            float4 a = *(const float4*)&KPs[tt * PAD + ty * 4];  // P[row][tt]
            float4 b = *(const float4*)&Vs[tt * 64 + tx * 4];
            fma44(o, a, b);
        }
    }

    float* C = g_ctx + ((size_t)bh * SS + q0) * KH;
#pragma unroll
    for (int i = 0; i < 4; i++) {
        float inv = 1.f / l[i];
        float4 v = make_float4(o[i][0] * inv, o[i][1] * inv, o[i][2] * inv, o[i][3] * inv);
        *(float4*)&C[(size_t)(ty * 4 + i) * KH + tx * 4] = v;
    }
}

// ---------------------------------------------------------------------------
// Kernel 3: output projection + head sum.
// out[B*S, D] = ctx_view[B*S, H*K] @ Wo_view[H*K, D]
// ---------------------------------------------------------------------------
__global__ __launch_bounds__(256) void out_gemm(const float* __restrict__ Wo,
                                                float* __restrict__ out) {
    __shared__ float As[16][PAD];
    __shared__ float Bs[16][64];

    const int t  = threadIdx.x;
    const int tx = t & 15, ty = t >> 4;
    const int m0 = blockIdx.x * 64;
    const int n0 = blockIdx.y * 64;

    float acc[4][4] = {};

    const int lc = t & 15, lr0 = t >> 4;
    const int bc = t & 63, br  = t >> 6;

    for (int k0 = 0; k0 < DD; k0 += 16) {
        const int h   = k0 >> 6;   // 16-chunk stays within one head
        const int kk0 = k0 & 63;
#pragma unroll
        for (int i = 0; i < 4; i++) {
            int r = lr0 + i * 16;
            int mrow = m0 + r;
            int b = mrow >> 11;          // S == 2048
            int s = mrow & 2047;
            As[lc][r] = g_ctx[(((size_t)(b * HH + h)) * SS + s) * KH + kk0 + lc];
        }
#pragma unroll
        for (int i = 0; i < 4; i++) {
            int rr = br + i * 4;
            Bs[rr][bc] = Wo[(size_t)(k0 + rr) * DD + n0 + bc];
        }
        __syncthreads();
#pragma unroll
        for (int kk = 0; kk < 16; kk++) {
            float4 a  = *(const float4*)&As[kk][ty * 4];
            float4 b4 = *(const float4*)&Bs[kk][tx * 4];
            fma44(acc, a, b4);
        }
        __syncthreads();
    }

#pragma unroll
    for (int i = 0; i < 4; i++) {
        float4 v = make_float4(acc[i][0], acc[i][1], acc[i][2], acc[i][3]);
        *(float4*)&out[(size_t)(m0 + ty * 4 + i) * DD + n0 + tx * 4] = v;
    }
}

// ---------------------------------------------------------------------------
extern "C" void kernel_launch(void* const* d_in, const int* in_sizes, int n_in,
                              void* d_out, int out_size) {
    const float* x  = (const float*)d_in[0];
    const float* Wq = (const float*)d_in[1];
    const float* Wk = (const float*)d_in[2];
    const float* Wv = (const float*)d_in[3];
    const float* Wo = (const float*)d_in[4];
    float* out = (float*)d_out;

    cudaFuncSetAttribute(attn_kernel, cudaFuncAttributeMaxDynamicSharedMemorySize,
                         SMEM_ATTN_BYTES);

    qkv_gemm<<<dim3(SS / 64, NBH, 3), 256>>>(x, Wq, Wk, Wv);
    attn_kernel<<<dim3(SS / 64, NBH), 256, SMEM_ATTN_BYTES>>>();
    out_gemm<<<dim3((BB * SS) / 64, DD / 64), 256>>>(Wo, out);
}